// round 13
// baseline (speedup 1.0000x reference)
#include <cuda_runtime.h>
#include <math.h>

#define NROWS    32768
#define DD       256
#define KK       1024
#define BM       32
#define BK       128
#define DSUB     64
#define NTHREADS 256
#define NBLOCKS  (NROWS / BM)

#define SCAL_OFF 8388608         // 32768*256
#define IDX_OFF  8388612
#define FULL_OUT (8388608 + 4 + 32768)

// ---- global scratch (no allocs allowed) ----
__device__ float  g_avgp[KK];
__device__ float  g_sent;
__device__ float  g_diff;
__device__ float  g_cnorm[KK];

// ---- smem layout in floats ----
#define DSM_OFF   0          // 32*1024 = 32768
#define XS_OFF    32768      // 32*256  = 8192
#define CS_OFF    40960      // 128*68  = 8704
#define CN_OFF    49664      // 128
#define XN_OFF    49792      // 32
#define REDD_OFF  49824      // 32*32 = 1024
#define REDI_OFF  50848      // 32*32 = 1024 (ints)
#define DMIN_OFF  51872      // 32
#define IMIN_OFF  51904      // 32 (ints)
#define ZS_OFF    51936      // 32
#define IZ_OFF    51968      // 32
#define SENT_OFF  52000      // 32
#define SMEM_FLOATS 52032    // 208128 bytes

__global__ void k_zero() {
    int t = threadIdx.x;
    if (t < KK) g_avgp[t] = 0.f;
    if (t == 0) { g_sent = 0.f; g_diff = 0.f; }
}

// ||c_k||^2 -- XLA GPU x2-vectorized row-reduction emulation:
// lane loads float2 at element 2*lane + 64*i (i=0..3), accumulates the pair
// sequentially into ONE accumulator with fma.rn (NVPTX contraction), then
// shfl_down tree 16..1 of plain rn adds.
__global__ void k_cnorm(const float* __restrict__ cb) {
    int k = blockIdx.x, l = threadIdx.x;
    const float2* c2 = (const float2*)(cb + (size_t)k * DD);
    float p = 0.f;
#pragma unroll
    for (int i = 0; i < 4; ++i) {
        float2 v = c2[l + 32 * i];          // elements 2l+64i, 2l+64i+1
        p = fmaf(v.x, v.x, p);
        p = fmaf(v.y, v.y, p);
    }
#pragma unroll
    for (int off = 16; off; off >>= 1)
        p = __fadd_rn(p, __shfl_down_sync(0xffffffffu, p, off));
    if (l == 0) g_cnorm[k] = p;
}

__global__ void __launch_bounds__(NTHREADS, 1)
k_main(const float* __restrict__ x, const float* __restrict__ cb,
       float* __restrict__ out, int write_extra)
{
    extern __shared__ float sm[];
    float* dsm  = sm + DSM_OFF;
    float* xs   = sm + XS_OFF;
    float* cs   = sm + CS_OFF;
    float* cns  = sm + CN_OFF;
    float* xn   = sm + XN_OFF;
    float* redd = sm + REDD_OFF;
    int*   redi = (int*)(sm + REDI_OFF);
    float* dmin = sm + DMIN_OFF;
    int*   imin = (int*)(sm + IMIN_OFF);
    float* Zs   = sm + ZS_OFF;
    float* iZ   = sm + IZ_OFF;
    float* sent = sm + SENT_OFF;

    const int tid = threadIdx.x;
    const int gr0 = blockIdx.x * BM;

    float4* xs4 = (float4*)xs;
    float4* cs4 = (float4*)cs;
    const float4* cb4 = (const float4*)cb;
    const float4* x4  = (const float4*)(x + (size_t)gr0 * DD);

    // load x tile [32][256]
#pragma unroll
    for (int i = 0; i < 8; ++i) xs4[tid + i * 256] = x4[tid + i * 256];
    __syncthreads();

    // per-row ||x||^2 -- same XLA x2-vectorized row-reduce realization:
    // one warp per row, float2 at 2*lane + 64*i, sequential-pair fma into one
    // accumulator, shfl_down tree 16..1.
    {
        int w = tid >> 5, lane = tid & 31;
        for (int rr = 0; rr < 4; ++rr) {
            int r = rr * 8 + w;
            const float2* xr2 = (const float2*)(xs + r * DD);
            float p = 0.f;
#pragma unroll
            for (int i = 0; i < 4; ++i) {
                float2 v = xr2[lane + 32 * i];
                p = fmaf(v.x, v.x, p);
                p = fmaf(v.y, v.y, p);
            }
#pragma unroll
            for (int off = 16; off; off >>= 1)
                p = __fadd_rn(p, __shfl_down_sync(0xffffffffu, p, off));
            if (lane == 0) xn[r] = p;
        }
    }

    const int trow = tid >> 5;      // 0..7
    const int tcol = tid & 31;      // 0..31
    const int r0 = trow * 4;

    float bd[4]; int bi[4];
#pragma unroll
    for (int i = 0; i < 4; ++i) { bd[i] = 3.4e38f; bi[i] = 0; }

    // ---- distance GEMM: 32 rows x 1024 codes ----
    // Per-output accumulation: single register, FFMA, k ascending 0..255 --
    // matching cuBLAS SGEMM's per-element accumulation order.
    for (int kc = 0; kc < KK; kc += BK) {
        __syncthreads();                       // protect cns/cs/xn readers
        if (tid < BK) cns[tid] = g_cnorm[kc + tid];

        float acc[4][4];
#pragma unroll
        for (int i = 0; i < 4; ++i)
#pragma unroll
            for (int j = 0; j < 4; ++j) acc[i][j] = 0.f;

        for (int ds = 0; ds < DD; ds += DSUB) {
            __syncthreads();
#pragma unroll
            for (int i = 0; i < 8; ++i) {
                int f = tid + i * 256;
                int row = f >> 4, c4i = f & 15;
                cs4[row * 17 + c4i] = cb4[(size_t)(kc + row) * 64 + (ds >> 2) + c4i];
            }
            __syncthreads();
            const int ds4 = ds >> 2;
#pragma unroll
            for (int d4 = 0; d4 < 16; ++d4) {
                float4 xv[4];
#pragma unroll
                for (int i = 0; i < 4; ++i) xv[i] = xs4[(r0 + i) * 64 + ds4 + d4];
#pragma unroll
                for (int j = 0; j < 4; ++j) {
                    float4 cv = cs4[(tcol + 32 * j) * 17 + d4];
#pragma unroll
                    for (int i = 0; i < 4; ++i) {
                        acc[i][j] = fmaf(xv[i].x, cv.x, acc[i][j]);
                        acc[i][j] = fmaf(xv[i].y, cv.y, acc[i][j]);
                        acc[i][j] = fmaf(xv[i].z, cv.z, acc[i][j]);
                        acc[i][j] = fmaf(xv[i].w, cv.w, acc[i][j]);
                    }
                }
            }
        }
        // epilogue: reference's exact fp32 chain:
        //   t  = fl(xn + cn)                  (FADD)
        //   d2 = fl(t - 2*dot)                (2*dot exact; single rounding)
        //   d  = fl32 IEEE sqrt(max(d2, 0))   (NOT fast-math sqrt)
#pragma unroll
        for (int j = 0; j < 4; ++j) {
            int kl = tcol + 32 * j;
            int k = kc + kl;
            float cn = cns[kl];
#pragma unroll
            for (int i = 0; i < 4; ++i) {
                float t  = __fadd_rn(xn[r0 + i], cn);
                float d2 = __fadd_rn(t, __fmul_rn(-2.0f, acc[i][j]));
                float d  = __fsqrt_rn(fmaxf(d2, 0.f));
                dsm[(r0 + i) * KK + k] = d;
                if (d < bd[i]) { bd[i] = d; bi[i] = k; }
            }
        }
    }

    // ---- row argmin reduction across 32 col-threads (first index on ties) ----
#pragma unroll
    for (int i = 0; i < 4; ++i) {
        redd[(r0 + i) * 32 + tcol] = bd[i];
        redi[(r0 + i) * 32 + tcol] = bi[i];
    }
    __syncthreads();
    if (tid < 32) {
        float best = redd[tid * 32]; int besti = redi[tid * 32];
        for (int c = 1; c < 32; ++c) {
            float v = redd[tid * 32 + c]; int vi = redi[tid * 32 + c];
            if (v < best || (v == best && vi < besti)) { best = v; besti = vi; }
        }
        dmin[tid] = best; imin[tid] = besti;
    }
    __syncthreads();

    // ---- pass B1: per-row Z = sum e, W = sum e*a; overwrite dsm with e ----
    {
        int r = tid >> 3, l = tid & 7;
        float dm = dmin[r];
        float z = 0.f, w = 0.f;
        float* drow = dsm + r * KK;
#pragma unroll 4
        for (int i = 0; i < 128; ++i) {
            int k = l + (i << 3);
            float d = drow[k];
            float a = (dm - d) * 100.0f;     // 1/T, T = 0.01
            float e = __expf(a);
            z += e; w = fmaf(e, a, w);
            drow[k] = e;
        }
#pragma unroll
        for (int off = 4; off; off >>= 1) {
            z += __shfl_down_sync(0xffffffffu, z, off, 8);
            w += __shfl_down_sync(0xffffffffu, w, off, 8);
        }
        if (l == 0) { Zs[r] = z; sent[r] = logf(z) - w / z; }
    }
    __syncthreads();
    if (tid < 32) {
        iZ[tid] = 1.0f / Zs[tid];
        float sv = sent[tid];
        float dv = dmin[tid] * dmin[tid];   // == sum_d (x-q)^2 for this row
#pragma unroll
        for (int off = 16; off; off >>= 1) {
            sv += __shfl_down_sync(0xffffffffu, sv, off);
            dv += __shfl_down_sync(0xffffffffu, dv, off);
        }
        if (tid == 0) { atomicAdd(&g_sent, sv); atomicAdd(&g_diff, dv); }
    }
    __syncthreads();

    // ---- pass B2: avg_probs accumulation (one atomic per column per block) ----
    {
        float4* dsm4 = (float4*)dsm;
        float s0 = 0.f, s1 = 0.f, s2 = 0.f, s3 = 0.f;
#pragma unroll 4
        for (int r = 0; r < 32; ++r) {
            float4 e = dsm4[r * 256 + tid];
            float z = iZ[r];
            s0 = fmaf(e.x, z, s0); s1 = fmaf(e.y, z, s1);
            s2 = fmaf(e.z, z, s2); s3 = fmaf(e.w, z, s3);
        }
        atomicAdd(&g_avgp[tid * 4 + 0], s0);
        atomicAdd(&g_avgp[tid * 4 + 1], s1);
        atomicAdd(&g_avgp[tid * 4 + 2], s2);
        atomicAdd(&g_avgp[tid * 4 + 3], s3);
    }

    // ---- quantized STE output + indices ----
    {
        float4* out4 = (float4*)out;
#pragma unroll
        for (int i = 0; i < 8; ++i) {
            int f = tid + i * 256;
            int r = f >> 6, c4i = f & 63;
            int ki = imin[r];
            float4 q  = cb4[(size_t)ki * 64 + c4i];
            float4 xv = xs4[r * 64 + c4i];
            float4 o;
            o.x = xv.x + (q.x - xv.x);
            o.y = xv.y + (q.y - xv.y);
            o.z = xv.z + (q.z - xv.z);
            o.w = xv.w + (q.w - xv.w);
            out4[(size_t)(gr0 + r) * 64 + c4i] = o;
        }
        if (write_extra && tid < 32) out[IDX_OFF + gr0 + tid] = (float)imin[tid];
    }
}

__global__ void k_final(float* __restrict__ outs) {
    __shared__ float red[256];
    int t = threadIdx.x;
    float acc = 0.f;
    for (int k = t; k < KK; k += 256) {
        float ap = g_avgp[k] * (1.0f / 32768.0f);
        acc += ap * logf(ap + 1e-5f);
    }
    red[t] = acc; __syncthreads();
    for (int s = 128; s; s >>= 1) { if (t < s) red[t] += red[t + s]; __syncthreads(); }
    if (t == 0) {
        float avg_ent = -red[0];
        float samp = g_sent * (1.0f / 32768.0f);
        float S = 0.5f * g_diff * (1.0f / 8388608.0f);  // codebook_loss
        float entl = (samp - avg_ent) * 0.1f;
        outs[0] = S + 0.25f * S + entl;  // vq_loss
        outs[1] = 0.25f * S;             // commit_loss
        outs[2] = S;                     // codebook_loss
        outs[3] = entl;                  // entropy_loss
    }
}

extern "C" void kernel_launch(void* const* d_in, const int* in_sizes, int n_in,
                              void* d_out, int out_size) {
    const float* x;
    const float* cb;
    if (in_sizes[0] == NROWS * DD) { x = (const float*)d_in[0]; cb = (const float*)d_in[1]; }
    else                            { x = (const float*)d_in[1]; cb = (const float*)d_in[0]; }
    float* out = (float*)d_out;
    int write_extra = (out_size >= FULL_OUT) ? 1 : 0;

    size_t smem = SMEM_FLOATS * sizeof(float);
    cudaFuncSetAttribute(k_main, cudaFuncAttributeMaxDynamicSharedMemorySize, (int)smem);

    k_zero<<<1, 1024>>>();
    k_cnorm<<<KK, 32>>>(cb);
    k_main<<<NBLOCKS, NTHREADS, smem>>>(x, cb, out, write_extra);
    if (write_extra) k_final<<<1, 256>>>(out + SCAL_OFF);
}

// round 14
// speedup vs baseline: 1.0121x; 1.0121x over previous
#include <cuda_runtime.h>
#include <math.h>

#define NROWS    32768
#define DD       256
#define KK       1024
#define BM       32
#define BK       512
#define DSUB     16
#define NTHREADS 256
#define NBLOCKS  (NROWS / BM)

#define SCAL_OFF 8388608         // 32768*256
#define IDX_OFF  8388612
#define FULL_OUT (8388608 + 4 + 32768)

// ---- global scratch (no allocs allowed) ----
__device__ float  g_avgp[KK];
__device__ float  g_sent;
__device__ float  g_diff;
__device__ float  g_cnorm[KK];

// ---- smem layout in floats ----
#define DSM_OFF    0          // 32*1024 = 32768
#define XS_OFF     32768      // 32*256  = 8192
#define XSPB_OFF   40960      // 32*36   = 1152   (x duplicated pairs, per ds-stage)
#define CST_OFF    42112      // 16*516  = 8256   (codebook dim-major, per ds-stage)
#define CNS_OFF    50368      // 512
#define XN_OFF     50880      // 32
#define REDD_OFF   50912      // 1024
#define REDI_OFF   51936      // 1024 (ints)
#define DMIN_OFF   52960      // 32
#define IMIN_OFF   52992      // 32 (ints)
#define ZS_OFF     53024      // 32
#define IZ_OFF     53056      // 32
#define SENT_OFF   53088      // 32
#define SMEM_FLOATS 53120     // 212480 bytes

#define XSPB_STRIDE 36        // floats per row (16 dup-pairs + pad), 144B = 16B-aligned
#define CST_STRIDE  516       // floats per dim row (512 codes + pad), 2064B = 16B-aligned

// packed dual FMA: two independent IEEE fma.rn.f32 lanes in one instruction.
#define FMA2(acc, a, b) \
    asm("fma.rn.f32x2 %0, %1, %2, %0;" : "+l"(acc) : "l"(a), "l"(b))

__global__ void k_zero() {
    int t = threadIdx.x;
    if (t < KK) g_avgp[t] = 0.f;
    if (t == 0) { g_sent = 0.f; g_diff = 0.f; }
}

// ||c_k||^2 -- XLA GPU x2-vectorized row-reduction emulation (DO NOT TOUCH):
// lane loads float2 at element 2*lane + 64*i, sequential-pair fma into one
// accumulator, then shfl_down tree 16..1 of plain rn adds.
__global__ void k_cnorm(const float* __restrict__ cb) {
    int k = blockIdx.x, l = threadIdx.x;
    const float2* c2 = (const float2*)(cb + (size_t)k * DD);
    float p = 0.f;
#pragma unroll
    for (int i = 0; i < 4; ++i) {
        float2 v = c2[l + 32 * i];
        p = fmaf(v.x, v.x, p);
        p = fmaf(v.y, v.y, p);
    }
#pragma unroll
    for (int off = 16; off; off >>= 1)
        p = __fadd_rn(p, __shfl_down_sync(0xffffffffu, p, off));
    if (l == 0) g_cnorm[k] = p;
}

__global__ void __launch_bounds__(NTHREADS, 1)
k_main(const float* __restrict__ x, const float* __restrict__ cb,
       float* __restrict__ out, int write_extra)
{
    extern __shared__ float sm[];
    float* dsm  = sm + DSM_OFF;
    float* xs   = sm + XS_OFF;
    float* xspb = sm + XSPB_OFF;
    float* cst  = sm + CST_OFF;
    float* cns  = sm + CNS_OFF;
    float* xn   = sm + XN_OFF;
    float* redd = sm + REDD_OFF;
    int*   redi = (int*)(sm + REDI_OFF);
    float* dmin = sm + DMIN_OFF;
    int*   imin = (int*)(sm + IMIN_OFF);
    float* Zs   = sm + ZS_OFF;
    float* iZ   = sm + IZ_OFF;
    float* sent = sm + SENT_OFF;

    const int tid = threadIdx.x;
    const int gr0 = blockIdx.x * BM;

    float4* xs4 = (float4*)xs;
    const float4* cb4 = (const float4*)cb;
    const float4* x4  = (const float4*)(x + (size_t)gr0 * DD);

    // load x tile [32][256]
#pragma unroll
    for (int i = 0; i < 8; ++i) xs4[tid + i * 256] = x4[tid + i * 256];
    __syncthreads();

    // per-row ||x||^2 -- XLA x2-vectorized row-reduce realization (DO NOT TOUCH)
    {
        int w = tid >> 5, lane = tid & 31;
        for (int rr = 0; rr < 4; ++rr) {
            int r = rr * 8 + w;
            const float2* xr2 = (const float2*)(xs + r * DD);
            float p = 0.f;
#pragma unroll
            for (int i = 0; i < 4; ++i) {
                float2 v = xr2[lane + 32 * i];
                p = fmaf(v.x, v.x, p);
                p = fmaf(v.y, v.y, p);
            }
#pragma unroll
            for (int off = 16; off; off >>= 1)
                p = __fadd_rn(p, __shfl_down_sync(0xffffffffu, p, off));
            if (lane == 0) xn[r] = p;
        }
    }

    const int trow = tid >> 5;      // 0..7 (warp id)
    const int tcol = tid & 31;      // 0..31 (lane)
    const int r0 = trow * 4;

    float bd[4]; int bi[4];
#pragma unroll
    for (int i = 0; i < 4; ++i) { bd[i] = 3.4e38f; bi[i] = 0; }

    // ---- distance GEMM: 32 rows x 1024 codes, packed f32x2 FMA ----
    // Each output keeps its OWN half of a b64 accumulator, updated with a
    // serial fma.rn chain over k ascending 0..255 -- bit-identical to the
    // scalar FFMA chain (cuBLAS per-output order). Codes per thread:
    // {128*g + 4*tcol + u : g=0..3, u=0..3} per kc tile.
    for (int kc = 0; kc < KK; kc += BK) {
        __syncthreads();
        cns[tid]       = g_cnorm[kc + tid];
        cns[tid + 256] = g_cnorm[kc + tid + 256];

        unsigned long long acc[4][8];
#pragma unroll
        for (int i = 0; i < 4; ++i)
#pragma unroll
            for (int j = 0; j < 8; ++j) acc[i][j] = 0ull;

        for (int ds = 0; ds < DD; ds += DSUB) {
            __syncthreads();
            // stage codebook sub-tile dim-major: cst[dim][code], 512 codes x 16 dims
#pragma unroll
            for (int i = 0; i < 8; ++i) {
                int idx = tid + i * 256;
                int code = idx >> 2, d4 = idx & 3;
                float4 v = cb4[(size_t)(kc + code) * 64 + (ds >> 2) + d4];
                float* dst = cst + (4 * d4) * CST_STRIDE + code;
                dst[0 * CST_STRIDE] = v.x;
                dst[1 * CST_STRIDE] = v.y;
                dst[2 * CST_STRIDE] = v.z;
                dst[3 * CST_STRIDE] = v.w;
            }
            // stage duplicated x pairs: xspb[row][kk] = (x, x)
#pragma unroll
            for (int j = 0; j < 2; ++j) {
                int e = tid + j * 256;
                int row = e >> 4, kk = e & 15;
                float v = xs[row * DD + ds + kk];
                *(float2*)(xspb + row * XSPB_STRIDE + kk * 2) = make_float2(v, v);
            }
            __syncthreads();

#pragma unroll
            for (int kk = 0; kk < DSUB; kk += 2) {
                ulonglong2 xp[4];
#pragma unroll
                for (int i = 0; i < 4; ++i)
                    xp[i] = *(const ulonglong2*)(xspb + (r0 + i) * XSPB_STRIDE + kk * 2);
                ulonglong2 cva[4], cvb[4];
#pragma unroll
                for (int g = 0; g < 4; ++g) {
                    cva[g] = *(const ulonglong2*)(cst + kk * CST_STRIDE + 4 * tcol + 128 * g);
                    cvb[g] = *(const ulonglong2*)(cst + (kk + 1) * CST_STRIDE + 4 * tcol + 128 * g);
                }
#pragma unroll
                for (int i = 0; i < 4; ++i) {
#pragma unroll
                    for (int g = 0; g < 4; ++g) {
                        FMA2(acc[i][2 * g],     xp[i].x, cva[g].x);
                        FMA2(acc[i][2 * g + 1], xp[i].x, cva[g].y);
                        FMA2(acc[i][2 * g],     xp[i].y, cvb[g].x);
                        FMA2(acc[i][2 * g + 1], xp[i].y, cvb[g].y);
                    }
                }
            }
        }

        // epilogue: reference's exact fp32 chain per output (DO NOT TOUCH):
        //   t = fl(xn + cn); d2 = fl(t - 2*dot); d = IEEE sqrt(max(d2,0))
        // scan u ascending within g ascending -> k ascending per thread.
#pragma unroll
        for (int g = 0; g < 4; ++g) {
#pragma unroll
            for (int i = 0; i < 4; ++i) {
                float dq[4];
#pragma unroll
                for (int u = 0; u < 4; ++u) {
                    unsigned long long a = acc[i][2 * g + (u >> 1)];
                    float dot = (u & 1) ? __uint_as_float((unsigned)(a >> 32))
                                        : __uint_as_float((unsigned)a);
                    int kl = 128 * g + 4 * tcol + u;
                    float t  = __fadd_rn(xn[r0 + i], cns[kl]);
                    float d2 = __fadd_rn(t, __fmul_rn(-2.0f, dot));
                    float d  = __fsqrt_rn(fmaxf(d2, 0.f));
                    dq[u] = d;
                    if (d < bd[i]) { bd[i] = d; bi[i] = kc + kl; }
                }
                *(float4*)(dsm + (r0 + i) * KK + kc + 128 * g + 4 * tcol) =
                    make_float4(dq[0], dq[1], dq[2], dq[3]);
            }
        }
    }

    // ---- row argmin reduction across 32 col-threads (first index on ties) ----
#pragma unroll
    for (int i = 0; i < 4; ++i) {
        redd[(r0 + i) * 32 + tcol] = bd[i];
        redi[(r0 + i) * 32 + tcol] = bi[i];
    }
    __syncthreads();
    if (tid < 32) {
        float best = redd[tid * 32]; int besti = redi[tid * 32];
        for (int c = 1; c < 32; ++c) {
            float v = redd[tid * 32 + c]; int vi = redi[tid * 32 + c];
            if (v < best || (v == best && vi < besti)) { best = v; besti = vi; }
        }
        dmin[tid] = best; imin[tid] = besti;
    }
    __syncthreads();

    // ---- pass B1: per-row Z = sum e, W = sum e*a; overwrite dsm with e ----
    {
        int r = tid >> 3, l = tid & 7;
        float dm = dmin[r];
        float z = 0.f, w = 0.f;
        float* drow = dsm + r * KK;
#pragma unroll 4
        for (int i = 0; i < 128; ++i) {
            int k = l + (i << 3);
            float d = drow[k];
            float a = (dm - d) * 100.0f;     // 1/T, T = 0.01
            float e = __expf(a);
            z += e; w = fmaf(e, a, w);
            drow[k] = e;
        }
#pragma unroll
        for (int off = 4; off; off >>= 1) {
            z += __shfl_down_sync(0xffffffffu, z, off, 8);
            w += __shfl_down_sync(0xffffffffu, w, off, 8);
        }
        if (l == 0) { Zs[r] = z; sent[r] = logf(z) - w / z; }
    }
    __syncthreads();
    if (tid < 32) {
        iZ[tid] = 1.0f / Zs[tid];
        float sv = sent[tid];
        float dv = dmin[tid] * dmin[tid];   // == sum_d (x-q)^2 for this row
#pragma unroll
        for (int off = 16; off; off >>= 1) {
            sv += __shfl_down_sync(0xffffffffu, sv, off);
            dv += __shfl_down_sync(0xffffffffu, dv, off);
        }
        if (tid == 0) { atomicAdd(&g_sent, sv); atomicAdd(&g_diff, dv); }
    }
    __syncthreads();

    // ---- pass B2: avg_probs accumulation (one atomic per column per block) ----
    {
        float4* dsm4 = (float4*)dsm;
        float s0 = 0.f, s1 = 0.f, s2 = 0.f, s3 = 0.f;
#pragma unroll 4
        for (int r = 0; r < 32; ++r) {
            float4 e = dsm4[r * 256 + tid];
            float z = iZ[r];
            s0 = fmaf(e.x, z, s0); s1 = fmaf(e.y, z, s1);
            s2 = fmaf(e.z, z, s2); s3 = fmaf(e.w, z, s3);
        }
        atomicAdd(&g_avgp[tid * 4 + 0], s0);
        atomicAdd(&g_avgp[tid * 4 + 1], s1);
        atomicAdd(&g_avgp[tid * 4 + 2], s2);
        atomicAdd(&g_avgp[tid * 4 + 3], s3);
    }

    // ---- quantized STE output + indices ----
    {
        float4* out4 = (float4*)out;
#pragma unroll
        for (int i = 0; i < 8; ++i) {
            int f = tid + i * 256;
            int r = f >> 6, c4i = f & 63;
            int ki = imin[r];
            float4 q  = cb4[(size_t)ki * 64 + c4i];
            float4 xv = xs4[r * 64 + c4i];
            float4 o;
            o.x = xv.x + (q.x - xv.x);
            o.y = xv.y + (q.y - xv.y);
            o.z = xv.z + (q.z - xv.z);
            o.w = xv.w + (q.w - xv.w);
            out4[(size_t)(gr0 + r) * 64 + c4i] = o;
        }
        if (write_extra && tid < 32) out[IDX_OFF + gr0 + tid] = (float)imin[tid];
    }
}

__global__ void k_final(float* __restrict__ outs) {
    __shared__ float red[256];
    int t = threadIdx.x;
    float acc = 0.f;
    for (int k = t; k < KK; k += 256) {
        float ap = g_avgp[k] * (1.0f / 32768.0f);
        acc += ap * logf(ap + 1e-5f);
    }
    red[t] = acc; __syncthreads();
    for (int s = 128; s; s >>= 1) { if (t < s) red[t] += red[t + s]; __syncthreads(); }
    if (t == 0) {
        float avg_ent = -red[0];
        float samp = g_sent * (1.0f / 32768.0f);
        float S = 0.5f * g_diff * (1.0f / 8388608.0f);  // codebook_loss
        float entl = (samp - avg_ent) * 0.1f;
        outs[0] = S + 0.25f * S + entl;  // vq_loss
        outs[1] = 0.25f * S;             // commit_loss
        outs[2] = S;                     // codebook_loss
        outs[3] = entl;                  // entropy_loss
    }
}

extern "C" void kernel_launch(void* const* d_in, const int* in_sizes, int n_in,
                              void* d_out, int out_size) {
    const float* x;
    const float* cb;
    if (in_sizes[0] == NROWS * DD) { x = (const float*)d_in[0]; cb = (const float*)d_in[1]; }
    else                            { x = (const float*)d_in[1]; cb = (const float*)d_in[0]; }
    float* out = (float*)d_out;
    int write_extra = (out_size >= FULL_OUT) ? 1 : 0;

    size_t smem = SMEM_FLOATS * sizeof(float);
    cudaFuncSetAttribute(k_main, cudaFuncAttributeMaxDynamicSharedMemorySize, (int)smem);

    k_zero<<<1, 1024>>>();
    k_cnorm<<<KK, 32>>>(cb);
    k_main<<<NBLOCKS, NTHREADS, smem>>>(x, cb, out, write_extra);
    if (write_extra) k_final<<<1, 256>>>(out + SCAL_OFF);
}